// round 2
// baseline (speedup 1.0000x reference)
#include <cuda_runtime.h>

#define Bn 128
#define Tn 1024
#define Kn 16
#define STAGES 8
#define CH 32
#define NCHUNK (Tn/CH)

static __device__ __forceinline__ float ex2f(float x){ float r; asm("ex2.approx.f32 %0, %1;" : "=f"(r) : "f"(x)); return r; }
static __device__ __forceinline__ float lg2f(float x){ float r; asm("lg2.approx.f32 %0, %1;" : "=f"(r) : "f"(x)); return r; }
static __device__ __forceinline__ float rcpf(float x){ float r; asm("rcp.approx.f32 %0, %1;" : "=f"(r) : "f"(x)); return r; }
static __device__ __forceinline__ void cp16(unsigned s, const float* g){
  asm volatile("cp.async.ca.shared.global [%0], [%1], 16;" :: "r"(s), "l"(g) : "memory");
}

struct SmemT {
  float L[STAGES][Kn*Kn];   // logits ring, 1KB per stage
  float G[STAGES][Kn];      // gumbel ring
  float Y[2][CH][Kn];       // normalized y_t, double-buffered per chunk
  float Ll[2][CH][Kn];      // mixed logits l_t (normalized)
  float Wr[2][CH][Kn];      // (y_{t-1}^T logP)_j
};

__global__ void __launch_bounds__(256,1) fused_kernel(
 const float* __restrict__ logits, const float* __restrict__ gum,
 const float* __restrict__ Am, const float* __restrict__ Bmm,
 const float* __restrict__ Cm, const float* __restrict__ trP,
 float* __restrict__ oA, float* __restrict__ oB, float* __restrict__ oC,
 float* __restrict__ oLq, float* __restrict__ oLp)
{
  __shared__ SmemT sm;
  const int b = blockIdx.x;
  const int tid = threadIdx.x;
  const int wid = tid >> 5, lane = tid & 31;
  const float LOG2E = 1.4426950408889634f;
  const float LN2   = 0.69314718055994531f;
  const float C2L   = 2.0f * LOG2E;          // (1/tau) * log2(e), tau = 0.5

  if (wid == 7) {
    // ================= producer: sequential regime scan (1 warp) =================
    const int j = lane & 15;                 // lanes 16..31 mirror lanes 0..15
    const float* Lb = logits + (unsigned long long)b * Tn * 256;
    const float* Gb = gum    + (unsigned long long)b * Tn * 16;
    float logPc[Kn];
    #pragma unroll
    for (int k = 0; k < Kn; ++k) logPc[k] = lg2f(trP[k*Kn + j]) * LN2;  // log transP[k][j]

    unsigned sL0 = (unsigned)__cvta_generic_to_shared(&sm.L[0][0]);
    unsigned sG0 = (unsigned)__cvta_generic_to_shared(&sm.G[0][0]);
    // prologue: fill all 8 ring stages
    #pragma unroll
    for (int s = 0; s < STAGES; ++s) {
      cp16(sL0 + s*1024 + lane*32,      Lb + s*256 + lane*8);
      cp16(sL0 + s*1024 + lane*32 + 16, Lb + s*256 + lane*8 + 4);
      if (lane < 4) cp16(sG0 + s*64 + lane*16, Gb + s*16 + lane*4);
      asm volatile("cp.async.commit_group;" ::: "memory");
    }

    float e = 1.0f;  // unnormalized weights of y_{t-1}; e=1 <=> uniform 1/K
    for (int c = 0; c <= NCHUNK; ++c) {
      if (c < NCHUNK) {
        const int buf = c & 1;
        for (int i = 0; i < CH; ++i) {
          const int t = c*CH + i;
          const int st = t & (STAGES-1);
          asm volatile("cp.async.wait_group 7;" ::: "memory");
          __syncwarp();
          float Lc[Kn];
          #pragma unroll
          for (int k = 0; k < Kn; ++k) Lc[k] = sm.L[st][k*Kn + j];
          float gz = sm.G[st][j] * C2L;
          // refill ring stage t+8 (commit unconditionally to keep FIFO depth = 8).
          // Safe vs the reads above: warp is converged, so every lane's LDS has
          // issued before any lane issues cp.async; the DMA smem write lands
          // >=500cyc later while LDS completes in ~30cyc.
          { int tn = t + STAGES;
            if (tn < Tn) {
              int sn = tn & (STAGES-1);
              cp16(sL0 + sn*1024 + lane*32,      Lb + tn*256 + lane*8);
              cp16(sL0 + sn*1024 + lane*32 + 16, Lb + tn*256 + lane*8 + 4);
              if (lane < 4) cp16(sG0 + sn*64 + lane*16, Gb + tn*16 + lane*4);
            }
            asm volatile("cp.async.commit_group;" ::: "memory");
          }
          // ---- critical path: dual FMA chains fed by 16 shfl broadcasts ----
          float u = 0.f, S = 0.f, w = 0.f;
          #pragma unroll
          for (int k = 0; k < Kn; ++k) {
            float ek = __shfl_sync(0xffffffffu, e, k);
            u  = fmaf(ek, Lc[k],    u);   // S * l_j
            S += ek;                      // normalizer of e (= y_{t-1} unnorm)
            w  = fmaf(ek, logPc[k], w);   // S * (y_{t-1}^T logP)_j
          }
          float r  = rcpf(S);
          float en = ex2f(fmaf(u, r * C2L, gz));   // exp((l+g)/tau), next-state e
          // ---- off critical path: outputs for this step ----
          float l  = u * r;                        // normalized mixed logits
          float Se = en;
          #pragma unroll
          for (int d = 8; d; d >>= 1) Se += __shfl_xor_sync(0xffffffffu, Se, d);
          float rf = rcpf(Se);
          if (lane < Kn) {
            sm.Y [buf][i][j] = en * rf;            // y_t
            sm.Ll[buf][i][j] = l;
            sm.Wr[buf][i][j] = w * r;              // (y_{t-1}^T logP)_j
          }
          e = en;
        }
      }
      __syncthreads();
    }
  } else if (wid < 3) {
    // ================= mixer warps: A_seq / B_seq epilogue =================
    // 96 threads x float4 = 384 outputs per (b,t): [0,256)=A_seq elems, [256,384)=B_seq
    const int q = wid*32 + lane;
    const int base = q * 4;
    const bool isA = base < 256;
    float c0[Kn], c1[Kn], c2[Kn], c3[Kn];
    #pragma unroll
    for (int k = 0; k < Kn; ++k) {
      if (isA) {
        c0[k] = Am[k*256 + base];     c1[k] = Am[k*256 + base + 1];
        c2[k] = Am[k*256 + base + 2]; c3[k] = Am[k*256 + base + 3];
      } else {
        int eb = base - 256;
        c0[k] = Bmm[k*128 + eb];      c1[k] = Bmm[k*128 + eb + 1];
        c2[k] = Bmm[k*128 + eb + 2];  c3[k] = Bmm[k*128 + eb + 3];
      }
    }
    for (int c = 0; c <= NCHUNK; ++c) {
      if (c >= 1) {
        const int buf = (c-1) & 1;
        const int t0 = (c-1) * CH;
        for (int i = 0; i < CH; ++i) {
          float a0=0.f,a1=0.f,a2=0.f,a3=0.f;
          #pragma unroll
          for (int k = 0; k < Kn; ++k) {
            float yk = sm.Y[buf][i][k];            // LDS broadcast
            a0 = fmaf(yk, c0[k], a0); a1 = fmaf(yk, c1[k], a1);
            a2 = fmaf(yk, c2[k], a2); a3 = fmaf(yk, c3[k], a3);
          }
          unsigned long long t = (unsigned long long)(t0 + i);
          float4 v = make_float4(a0,a1,a2,a3);
          if (isA) *(float4*)(oA + ((unsigned long long)b*Tn + t)*256 + base) = v;
          else     *(float4*)(oB + ((unsigned long long)b*Tn + t)*128 + (base-256)) = v;
        }
      }
      __syncthreads();
    }
  } else if (wid == 4) {
    // ================= stats warp: log_q / log_p =================
    const int j = lane & 15;
    for (int c = 0; c <= NCHUNK; ++c) {
      if (c >= 1) {
        const int buf = (c-1) & 1;
        const int t0 = (c-1) * CH;
        for (int i = 0; i < CH; ++i) {
          const int t = t0 + i;
          float y  = sm.Y [buf][i][j];
          float l  = sm.Ll[buf][i][j];
          float wr = sm.Wr[buf][i][j];
          float sel = ex2f(l * LOG2E);   // exp(l_j), for logsumexp(l)
          float syl = y * l;             // -> sum y*l
          float slp = y * wr;            // -> y_{t-1}^T logP y_t
          #pragma unroll
          for (int d = 8; d; d >>= 1) {
            sel += __shfl_xor_sync(0xffffffffu, sel, d);
            syl += __shfl_xor_sync(0xffffffffu, syl, d);
            slp += __shfl_xor_sync(0xffffffffu, slp, d);
          }
          float lq = syl - lg2f(sel) * LN2;                 // sum y*(l - lse)
          float lp = (t == 0) ? -2.7725887222397811f : slp; // t=0: -log(K)
          if (lane == 0) {
            oLq[(unsigned long long)b*Tn + t] = lq;
            oLp[(unsigned long long)b*Tn + t] = lp;
          }
        }
      }
      __syncthreads();
    }
  } else {
    // wid 3 (keeps producer's SMSP3 clean), 5 (C_seq writer), 6: barrier-matched
    if (wid == 5) {
      for (int x = lane; x < 512; x += 32) oC[(unsigned long long)b*512 + x] = Cm[x];
    }
    for (int c = 0; c <= NCHUNK; ++c) __syncthreads();
  }
}

extern "C" void kernel_launch(void* const* d_in, const int* in_sizes, int n_in,
                              void* d_out, int out_size) {
  const float* logits = (const float*)d_in[0];
  const float* gum    = (const float*)d_in[1];
  const float* Am     = (const float*)d_in[2];
  const float* Bmm    = (const float*)d_in[3];
  const float* Cm     = (const float*)d_in[4];
  const float* trP    = (const float*)d_in[5];
  float* out = (float*)d_out;
  // output layout: A_seq | B_seq | C_seq | log_qseq | log_pseq
  float* oA  = out;                               // 128*1024*256
  float* oB  = out + 33554432ull;                 // 128*1024*128
  float* oC  = out + 50331648ull;                 // 128*512
  float* oLq = out + 50397184ull;                 // 128*1024
  float* oLp = out + 50528256ull;                 // 128*1024
  fused_kernel<<<Bn, 256>>>(logits, gum, Am, Bmm, Cm, trP, oA, oB, oC, oLq, oLp);
}